// round 13
// baseline (speedup 1.0000x reference)
#include <cuda_runtime.h>
#include <cuda_fp16.h>
#include <math.h>
#include <stdint.h>

// Problem constants
#define B_SZ    4
#define T_SZ    2048
#define D_MODEL 1024
#define NHEAD   16
#define DHEAD   64
#define D3      (3 * D_MODEL)
#define MROWS   (B_SZ * T_SZ)          // 8192

// Scratch (static device globals — allocation-free per harness rules)
__device__ __half g_qkvh[(size_t)MROWS * D3];       // fp16 qkv
__device__ __half g_atth[(size_t)MROWS * D_MODEL];  // fp16 attention out
__device__ __half g_xh[(size_t)MROWS * D_MODEL];    // fp16 x
__device__ __half g_wqh[(size_t)D3 * D_MODEL];      // fp16 qkv_w
__device__ __half g_woh[(size_t)D_MODEL * D_MODEL]; // fp16 out_w

// ---------------------------------------------------------------------------
// Helpers
// ---------------------------------------------------------------------------
__device__ __forceinline__ void mma_f16(
    float& d0, float& d1, float& d2, float& d3,
    unsigned a0, unsigned a1, unsigned a2, unsigned a3,
    unsigned b0, unsigned b1)
{
    asm("mma.sync.aligned.m16n8k16.row.col.f32.f16.f16.f32 "
        "{%0,%1,%2,%3}, {%4,%5,%6,%7}, {%8,%9}, {%0,%1,%2,%3};"
        : "+f"(d0), "+f"(d1), "+f"(d2), "+f"(d3)
        : "r"(a0), "r"(a1), "r"(a2), "r"(a3), "r"(b0), "r"(b1));
}

#define LDSM4(r0, r1, r2, r3, addr) \
    asm volatile("ldmatrix.sync.aligned.m8n8.x4.shared.b16 {%0,%1,%2,%3}, [%4];" \
                 : "=r"(r0), "=r"(r1), "=r"(r2), "=r"(r3) : "r"(addr))
#define LDSM4T(r0, r1, r2, r3, addr) \
    asm volatile("ldmatrix.sync.aligned.m8n8.x4.trans.shared.b16 {%0,%1,%2,%3}, [%4];" \
                 : "=r"(r0), "=r"(r1), "=r"(r2), "=r"(r3) : "r"(addr))

__device__ __forceinline__ void cp_async16(void* smem_dst, const void* gsrc) {
    unsigned saddr = (unsigned)__cvta_generic_to_shared(smem_dst);
    asm volatile("cp.async.ca.shared.global [%0], [%1], 16;"
                 :: "r"(saddr), "l"(gsrc));
}
#define CP_COMMIT()  asm volatile("cp.async.commit_group;")
#define CP_WAIT1()   asm volatile("cp.async.wait_group 1;")

// ---------------------------------------------------------------------------
// Pre-pass: fp32 -> fp16 (rn)
// ---------------------------------------------------------------------------
__global__ __launch_bounds__(256) void cvt_f32_f16(
    const float* __restrict__ in, __half* __restrict__ out, int n4)
{
    int i = blockIdx.x * blockDim.x + threadIdx.x;
    if (i < n4) {
        float4 v = ((const float4*)in)[i];
        ((__half2*)out)[2 * i]     = __floats2half2_rn(v.x, v.y);
        ((__half2*)out)[2 * i + 1] = __floats2half2_rn(v.z, v.w);
    }
}

// ---------------------------------------------------------------------------
// FP16 GEMM v5: 128x128 CTA, 256 threads (8 warps, 4x2), warp tile 32x64.
// launch_bounds(256,2) caps regs at 128 -> 2 CTAs/SM -> 16 warps/SM.
// K-chunk 64, cp.async 2-stage, stride-72 conflict-free ldmatrix.
// ---------------------------------------------------------------------------
#define HBK 64
#define HSTR 72
#define GSTG (128 * HSTR * 2)                  // stage bytes: 18432
#define GEMM_SMEM (4 * GSTG)                   // 73728

template <bool OUT_HALF>
__global__ __launch_bounds__(256, 2) void gemm_h(
    const __half* __restrict__ A, const __half* __restrict__ W,
    const float* __restrict__ bias, void* __restrict__ Cv,
    int M, int N, int K)
{
    extern __shared__ __half gsm[];
    __half* As = gsm;                          // [2][128][72]
    __half* Ws = gsm + 2 * 128 * HSTR;         // [2][128][72]

    const int tid  = threadIdx.x;
    const int lane = tid & 31;
    const int wid  = tid >> 5;
    const int wm = (wid >> 1) * 32;            // 0,32,64,96
    const int wn = (wid & 1) * 64;             // 0,64
    const int bm = blockIdx.y * 128;
    const int bn = blockIdx.x * 128;
    const int qr = lane >> 2;
    const int qc = lane & 3;

    const int arow = lane & 15;
    const int acol = (lane >> 4) * 8;
    const int brow = (lane & 7) + 8 * (lane >> 4);
    const int bsel = ((lane >> 3) & 1) * 8;

    const unsigned As_u = (unsigned)__cvta_generic_to_shared(As);
    const unsigned Ws_u = (unsigned)__cvta_generic_to_shared(Ws);

    unsigned a_ad[2], b_ad[4];
#pragma unroll
    for (int mt = 0; mt < 2; mt++)
        a_ad[mt] = As_u + ((wm + mt * 16 + arow) * HSTR + acol) * 2u;
#pragma unroll
    for (int p = 0; p < 4; p++)
        b_ad[p] = Ws_u + ((wn + p * 16 + brow) * HSTR + bsel) * 2u;

    const __half* Abase = A + (size_t)bm * K;
    const __half* Wbase = W + (size_t)bn * K;

    float acc[2][8][4];
#pragma unroll
    for (int mt = 0; mt < 2; mt++)
#pragma unroll
        for (int nt = 0; nt < 8; nt++)
#pragma unroll
            for (int r = 0; r < 4; r++) acc[mt][nt][r] = 0.f;

    const int NIT = K / HBK;   // 16

#define G_FILL(sidx, koff)                                                    \
    do {                                                                      \
        __half* Ad = As + (sidx) * 128 * HSTR;                                \
        __half* Wd = Ws + (sidx) * 128 * HSTR;                                \
        _Pragma("unroll")                                                     \
        for (int i = 0; i < 4; i++) {                                         \
            const int idx = tid + i * 256;        /* 0..1023 */               \
            const int row = idx >> 3, c16 = idx & 7;                          \
            cp_async16(Ad + row * HSTR + c16 * 8,                             \
                       Abase + (size_t)row * K + (koff) + c16 * 8);           \
            cp_async16(Wd + row * HSTR + c16 * 8,                             \
                       Wbase + (size_t)row * K + (koff) + c16 * 8);           \
        }                                                                     \
        CP_COMMIT();                                                          \
    } while (0)

    G_FILL(0, 0);

    for (int it = 0; it < NIT; it++) {
        const int s = it & 1;
        __syncthreads();
        if (it + 1 < NIT) {
            G_FILL(1 - s, (it + 1) * HBK);
        } else {
            CP_COMMIT();
        }
        CP_WAIT1();
        __syncthreads();

        const unsigned so = (unsigned)(s * GSTG);
#pragma unroll
        for (int ks = 0; ks < 4; ks++) {
            const unsigned kb = so + ks * 32u;
            unsigned af[2][4];
#pragma unroll
            for (int mt = 0; mt < 2; mt++)
                LDSM4(af[mt][0], af[mt][1], af[mt][2], af[mt][3], a_ad[mt] + kb);
            unsigned bf[8][2];
#pragma unroll
            for (int p = 0; p < 4; p++)
                LDSM4(bf[2 * p][0], bf[2 * p][1], bf[2 * p + 1][0], bf[2 * p + 1][1],
                      b_ad[p] + kb);
#pragma unroll
            for (int mt = 0; mt < 2; mt++)
#pragma unroll
                for (int nt = 0; nt < 8; nt++)
                    mma_f16(acc[mt][nt][0], acc[mt][nt][1],
                            acc[mt][nt][2], acc[mt][nt][3],
                            af[mt][0], af[mt][1], af[mt][2], af[mt][3],
                            bf[nt][0], bf[nt][1]);
        }
    }
#undef G_FILL

#pragma unroll
    for (int nt = 0; nt < 8; nt++) {
        const int col = bn + wn + nt * 8 + 2 * qc;
        const float2 bv = *(const float2*)(bias + col);
#pragma unroll
        for (int mt = 0; mt < 2; mt++) {
            const int r0 = bm + wm + mt * 16 + qr;
            if (OUT_HALF) {
                __half* C = (__half*)Cv;
                *(__half2*)(C + (size_t)r0 * N + col) =
                    __floats2half2_rn(acc[mt][nt][0] + bv.x, acc[mt][nt][1] + bv.y);
                *(__half2*)(C + (size_t)(r0 + 8) * N + col) =
                    __floats2half2_rn(acc[mt][nt][2] + bv.x, acc[mt][nt][3] + bv.y);
            } else {
                float* C = (float*)Cv;
                *(float2*)(C + (size_t)r0 * N + col) =
                    make_float2(acc[mt][nt][0] + bv.x, acc[mt][nt][1] + bv.y);
                *(float2*)(C + (size_t)(r0 + 8) * N + col) =
                    make_float2(acc[mt][nt][2] + bv.x, acc[mt][nt][3] + bv.y);
            }
        }
    }
}

// ---------------------------------------------------------------------------
// FP16 flash attention v6: 128-query tile, 256 threads (8 warps),
// warp tile 16x64. launch_bounds(256,2) -> 16 warps/SM.
// K/V double-buffered; P in registers (R12); Q fragments hoisted.
// ---------------------------------------------------------------------------
#define AQ   128
#define ASTR 72
#define KVSTG (64 * ASTR * 2)                  // 9216 bytes per K/V stage
// layout: Q(128) | K0(64) | K1(64) | V0(64) | V1(64)  rows x 72 halves
#define ATT_SMEM ((AQ + 4 * 64) * ASTR * 2)    // 55296

__global__ __launch_bounds__(256, 2) void attn_h(
    const __half* __restrict__ qkv, __half* __restrict__ out)
{
    extern __shared__ __half smh[];
    __half* Qs = smh;                          // 128 x 72
    __half* Ks = Qs + AQ * ASTR;               // 2 x 64 x 72
    __half* Vs = Ks + 2 * 64 * ASTR;           // 2 x 64 x 72

    const int bh = blockIdx.y;
    const int b  = bh >> 4;
    const int h  = bh & 15;
    const int q0 = blockIdx.x * AQ;

    const int tid  = threadIdx.x;
    const int lane = tid & 31;
    const int wid  = tid >> 5;
    const int wrow = wid * 16;                 // warp owns 16 query rows
    const int qr = lane >> 2;
    const int qc = lane & 3;

    const int arow = lane & 15;
    const int acol = (lane >> 4) * 8;
    const int brow = (lane & 7) + 8 * (lane >> 4);
    const int bsel = ((lane >> 3) & 1) * 8;
    const int vrow = (lane & 7) + 8 * ((lane >> 3) & 1);
    const int vsel = (lane >> 4) * 8;

    const unsigned Qs_u = (unsigned)__cvta_generic_to_shared(Qs);
    const unsigned Ks_u = (unsigned)__cvta_generic_to_shared(Ks);
    const unsigned Vs_u = (unsigned)__cvta_generic_to_shared(Vs);

    const unsigned q_ad = Qs_u + ((wrow + arow) * ASTR + acol) * 2u;
    unsigned k_ad[4], v_ad[4];
#pragma unroll
    for (int p = 0; p < 4; p++) {
        k_ad[p] = Ks_u + ((p * 16 + brow) * ASTR + bsel) * 2u;
        v_ad[p] = Vs_u + (vrow * ASTR + p * 16 + vsel) * 2u;
    }

    const __half* base = qkv + (size_t)b * T_SZ * D3;
    const int hoff = h * DHEAD;

#define A_FILL(sidx, k0)                                                      \
    do {                                                                      \
        __half* Kd = Ks + (sidx) * 64 * ASTR;                                 \
        __half* Vd = Vs + (sidx) * 64 * ASTR;                                 \
        _Pragma("unroll")                                                     \
        for (int i = 0; i < 2; i++) {                                         \
            const int idx = tid + i * 256;       /* 0..511 */                 \
            const int row = idx >> 3, c8 = idx & 7;                           \
            const __half* rp = base + (size_t)((k0) + row) * D3 + hoff + c8 * 8; \
            cp_async16(Kd + row * ASTR + c8 * 8, rp + D_MODEL);               \
            cp_async16(Vd + row * ASTR + c8 * 8, rp + 2 * D_MODEL);           \
        }                                                                     \
        CP_COMMIT();                                                          \
    } while (0)

    // Load Q (128x64 halves) to smem, scaled by 1/8 (exponent-only, exact)
    const __half2 qscale = __float2half2_rn(0.125f);
#pragma unroll
    for (int i = 0; i < 4; i++) {
        const int fidx = tid + i * 256;        // 0..1023
        const int row = fidx >> 3;
        const int c8  = fidx & 7;
        const __half2* src = (const __half2*)(base + (size_t)(q0 + row) * D3 + hoff + c8 * 8);
        __half2* dst = (__half2*)(Qs + row * ASTR + c8 * 8);
        dst[0] = __hmul2(src[0], qscale);
        dst[1] = __hmul2(src[1], qscale);
        dst[2] = __hmul2(src[2], qscale);
        dst[3] = __hmul2(src[3], qscale);
    }

    A_FILL(0, 0);                              // prefetch K/V tile 0
    __syncthreads();                           // Q stores visible

    // Hoist loop-invariant Q A-fragments (4 ksteps)
    unsigned qf[4][4];
#pragma unroll
    for (int ks = 0; ks < 4; ks++)
        LDSM4(qf[ks][0], qf[ks][1], qf[ks][2], qf[ks][3], q_ad + ks * 32u);

    float miA = -INFINITY, miB = -INFINITY;
    float liA = 0.f, liB = 0.f;
    float oacc[8][4];
#pragma unroll
    for (int nt = 0; nt < 8; nt++)
#pragma unroll
        for (int r = 0; r < 4; r++) oacc[nt][r] = 0.f;

    const int NKT = T_SZ / 64;                 // 32 key tiles

    for (int kt = 0; kt < NKT; kt++) {
        const int s = kt & 1;
        __syncthreads();                       // stage 1-s consumers done
        if (kt + 1 < NKT) {
            A_FILL(1 - s, (kt + 1) * 64);
        } else {
            CP_COMMIT();
        }
        CP_WAIT1();                            // stage s arrived
        __syncthreads();

        const unsigned soff = (unsigned)(s * KVSTG);

        // ---- S = (Q/8) K^T ----
        float sacc[8][4];
#pragma unroll
        for (int nt = 0; nt < 8; nt++)
#pragma unroll
            for (int r = 0; r < 4; r++) sacc[nt][r] = 0.f;

#pragma unroll
        for (int ks = 0; ks < 4; ks++) {
            unsigned bf[8][2];
#pragma unroll
            for (int p = 0; p < 4; p++)
                LDSM4(bf[2 * p][0], bf[2 * p][1], bf[2 * p + 1][0], bf[2 * p + 1][1],
                      k_ad[p] + ks * 32u + soff);
#pragma unroll
            for (int nt = 0; nt < 8; nt++)
                mma_f16(sacc[nt][0], sacc[nt][1], sacc[nt][2], sacc[nt][3],
                        qf[ks][0], qf[ks][1], qf[ks][2], qf[ks][3],
                        bf[nt][0], bf[nt][1]);
        }

        // ---- online softmax; P stays in registers as O-mma A-fragments ----
        unsigned pf01[8], pf23[8];
        {
            float mA = -INFINITY, mB = -INFINITY;
#pragma unroll
            for (int nt = 0; nt < 8; nt++) {
                mA = fmaxf(mA, fmaxf(sacc[nt][0], sacc[nt][1]));
                mB = fmaxf(mB, fmaxf(sacc[nt][2], sacc[nt][3]));
            }
            mA = fmaxf(mA, __shfl_xor_sync(0xffffffffu, mA, 1));
            mA = fmaxf(mA, __shfl_xor_sync(0xffffffffu, mA, 2));
            mB = fmaxf(mB, __shfl_xor_sync(0xffffffffu, mB, 1));
            mB = fmaxf(mB, __shfl_xor_sync(0xffffffffu, mB, 2));
            const float mnA = fmaxf(miA, mA);
            const float mnB = fmaxf(miB, mB);
            const float corrA = __expf(miA - mnA);
            const float corrB = __expf(miB - mnB);

            float psA = 0.f, psB = 0.f;
#pragma unroll
            for (int nt = 0; nt < 8; nt++) {
                __half2 h01 = __floats2half2_rn(__expf(sacc[nt][0] - mnA),
                                                __expf(sacc[nt][1] - mnA));
                __half2 h23 = __floats2half2_rn(__expf(sacc[nt][2] - mnB),
                                                __expf(sacc[nt][3] - mnB));
                pf01[nt] = *(unsigned*)&h01;
                pf23[nt] = *(unsigned*)&h23;
                float2 f01 = __half22float2(h01);
                float2 f23 = __half22float2(h23);
                psA += f01.x + f01.y;
                psB += f23.x + f23.y;
            }
            psA += __shfl_xor_sync(0xffffffffu, psA, 1);
            psA += __shfl_xor_sync(0xffffffffu, psA, 2);
            psB += __shfl_xor_sync(0xffffffffu, psB, 1);
            psB += __shfl_xor_sync(0xffffffffu, psB, 2);
            liA = liA * corrA + psA;
            liB = liB * corrB + psB;
            miA = mnA; miB = mnB;

#pragma unroll
            for (int nt = 0; nt < 8; nt++) {
                oacc[nt][0] *= corrA; oacc[nt][1] *= corrA;
                oacc[nt][2] *= corrB; oacc[nt][3] *= corrB;
            }
        }

        // ---- O += P V (P A-frags straight from registers) ----
#pragma unroll
        for (int ks = 0; ks < 4; ks++) {
            const unsigned kbV = ks * 16u * ASTR * 2u + soff;
            unsigned vf[8][2];
#pragma unroll
            for (int p = 0; p < 4; p++)
                LDSM4T(vf[2 * p][0], vf[2 * p][1], vf[2 * p + 1][0], vf[2 * p + 1][1],
                       v_ad[p] + kbV);
#pragma unroll
            for (int nt = 0; nt < 8; nt++)
                mma_f16(oacc[nt][0], oacc[nt][1], oacc[nt][2], oacc[nt][3],
                        pf01[2 * ks], pf23[2 * ks],
                        pf01[2 * ks + 1], pf23[2 * ks + 1],
                        vf[nt][0], vf[nt][1]);
        }
    }
#undef A_FILL

    // epilogue -> fp16
    {
        const float invA = 1.f / liA;
        const float invB = 1.f / liB;
        const int rowA = q0 + wrow + qr;
        __half* opA = out + (size_t)(b * T_SZ + rowA) * D_MODEL + hoff;
        __half* opB = opA + (size_t)8 * D_MODEL;
#pragma unroll
        for (int nt = 0; nt < 8; nt++) {
            const int col = nt * 8 + 2 * qc;
            *(__half2*)(opA + col) =
                __floats2half2_rn(oacc[nt][0] * invA, oacc[nt][1] * invA);
            *(__half2*)(opB + col) =
                __floats2half2_rn(oacc[nt][2] * invB, oacc[nt][3] * invB);
        }
    }
}

// ---------------------------------------------------------------------------
// Launch
// ---------------------------------------------------------------------------
extern "C" void kernel_launch(void* const* d_in, const int* in_sizes, int n_in,
                              void* d_out, int out_size)
{
    const float* x     = (const float*)d_in[0];
    const float* qkv_w = (const float*)d_in[1];
    const float* qkv_b = (const float*)d_in[2];
    const float* out_w = (const float*)d_in[3];
    const float* out_b = (const float*)d_in[4];
    float* out = (float*)d_out;

    __half *qkvh, *atth, *xh, *wqh, *woh;
    cudaGetSymbolAddress((void**)&qkvh, g_qkvh);
    cudaGetSymbolAddress((void**)&atth, g_atth);
    cudaGetSymbolAddress((void**)&xh, g_xh);
    cudaGetSymbolAddress((void**)&wqh, g_wqh);
    cudaGetSymbolAddress((void**)&woh, g_woh);

    cudaFuncSetAttribute(gemm_h<true>, cudaFuncAttributeMaxDynamicSharedMemorySize,
                         GEMM_SMEM);
    cudaFuncSetAttribute(gemm_h<false>, cudaFuncAttributeMaxDynamicSharedMemorySize,
                         GEMM_SMEM);
    cudaFuncSetAttribute(attn_h, cudaFuncAttributeMaxDynamicSharedMemorySize,
                         ATT_SMEM);

    // 0) fp32 -> fp16 pre-pass
    {
        const int n1 = MROWS * D_MODEL / 4;
        const int n2 = D3 * D_MODEL / 4;
        const int n3 = D_MODEL * D_MODEL / 4;
        cvt_f32_f16<<<(n1 + 255) / 256, 256>>>(x, xh, n1);
        cvt_f32_f16<<<(n2 + 255) / 256, 256>>>(qkv_w, wqh, n2);
        cvt_f32_f16<<<(n3 + 255) / 256, 256>>>(out_w, woh, n3);
    }

    // 1) QKV projection -> fp16 qkv
    gemm_h<true><<<dim3(D3 / 128, MROWS / 128), 256, GEMM_SMEM>>>(
        xh, wqh, qkv_b, qkvh, MROWS, D3, D_MODEL);

    // 2) Attention -> fp16
    attn_h<<<dim3(T_SZ / AQ, B_SZ * NHEAD), 256, ATT_SMEM>>>(qkvh, atth);

    // 3) Output projection -> fp32 out
    gemm_h<false><<<dim3(D_MODEL / 128, MROWS / 128), 256, GEMM_SMEM>>>(
        atth, woh, out_b, out, MROWS, D_MODEL, D_MODEL);
}

// round 14
// speedup vs baseline: 1.0660x; 1.0660x over previous
#include <cuda_runtime.h>
#include <cuda_fp16.h>
#include <math.h>
#include <stdint.h>

// Problem constants
#define B_SZ    4
#define T_SZ    2048
#define D_MODEL 1024
#define NHEAD   16
#define DHEAD   64
#define D3      (3 * D_MODEL)
#define MROWS   (B_SZ * T_SZ)          // 8192

// Scratch (static device globals — allocation-free per harness rules)
__device__ __half g_qkvh[(size_t)MROWS * D3];       // fp16 qkv
__device__ __half g_atth[(size_t)MROWS * D_MODEL];  // fp16 attention out
__device__ __half g_xh[(size_t)MROWS * D_MODEL];    // fp16 x
__device__ __half g_wqh[(size_t)D3 * D_MODEL];      // fp16 qkv_w
__device__ __half g_woh[(size_t)D_MODEL * D_MODEL]; // fp16 out_w

// ---------------------------------------------------------------------------
// Helpers
// ---------------------------------------------------------------------------
__device__ __forceinline__ void mma_f16(
    float& d0, float& d1, float& d2, float& d3,
    unsigned a0, unsigned a1, unsigned a2, unsigned a3,
    unsigned b0, unsigned b1)
{
    asm("mma.sync.aligned.m16n8k16.row.col.f32.f16.f16.f32 "
        "{%0,%1,%2,%3}, {%4,%5,%6,%7}, {%8,%9}, {%0,%1,%2,%3};"
        : "+f"(d0), "+f"(d1), "+f"(d2), "+f"(d3)
        : "r"(a0), "r"(a1), "r"(a2), "r"(a3), "r"(b0), "r"(b1));
}

#define LDSM4(r0, r1, r2, r3, addr) \
    asm volatile("ldmatrix.sync.aligned.m8n8.x4.shared.b16 {%0,%1,%2,%3}, [%4];" \
                 : "=r"(r0), "=r"(r1), "=r"(r2), "=r"(r3) : "r"(addr))
#define LDSM4T(r0, r1, r2, r3, addr) \
    asm volatile("ldmatrix.sync.aligned.m8n8.x4.trans.shared.b16 {%0,%1,%2,%3}, [%4];" \
                 : "=r"(r0), "=r"(r1), "=r"(r2), "=r"(r3) : "r"(addr))

__device__ __forceinline__ void cp_async16(void* smem_dst, const void* gsrc) {
    unsigned saddr = (unsigned)__cvta_generic_to_shared(smem_dst);
    asm volatile("cp.async.ca.shared.global [%0], [%1], 16;"
                 :: "r"(saddr), "l"(gsrc));
}
#define CP_COMMIT()  asm volatile("cp.async.commit_group;")
#define CP_WAIT0()   asm volatile("cp.async.wait_group 0;")

// ---------------------------------------------------------------------------
// Pre-pass: fp32 -> fp16 (rn)
// ---------------------------------------------------------------------------
__global__ __launch_bounds__(256) void cvt_f32_f16(
    const float* __restrict__ in, __half* __restrict__ out, int n4)
{
    int i = blockIdx.x * blockDim.x + threadIdx.x;
    if (i < n4) {
        float4 v = ((const float4*)in)[i];
        ((__half2*)out)[2 * i]     = __floats2half2_rn(v.x, v.y);
        ((__half2*)out)[2 * i + 1] = __floats2half2_rn(v.z, v.w);
    }
}

// ---------------------------------------------------------------------------
// FP16 GEMM v6: R12 structure (128 thr, 4 warps, warp tile 64x64) with ONE
// barrier per K-chunk:  wait_group 0 -> syncthreads -> refill -> compute.
// ---------------------------------------------------------------------------
#define HBK 64
#define HSTR 72
#define GSTG (128 * HSTR * 2)                  // stage bytes: 18432
#define GEMM_SMEM (4 * GSTG)                   // 73728

template <bool OUT_HALF>
__global__ __launch_bounds__(128) void gemm_h(
    const __half* __restrict__ A, const __half* __restrict__ W,
    const float* __restrict__ bias, void* __restrict__ Cv,
    int M, int N, int K)
{
    extern __shared__ __half gsm[];
    __half* As = gsm;                          // [2][128][72]
    __half* Ws = gsm + 2 * 128 * HSTR;         // [2][128][72]

    const int tid  = threadIdx.x;
    const int lane = tid & 31;
    const int wid  = tid >> 5;
    const int wm = (wid >> 1) * 64;
    const int wn = (wid & 1) * 64;
    const int bm = blockIdx.y * 128;
    const int bn = blockIdx.x * 128;
    const int qr = lane >> 2;
    const int qc = lane & 3;

    const int arow = lane & 15;
    const int acol = (lane >> 4) * 8;
    const int brow = (lane & 7) + 8 * (lane >> 4);
    const int bsel = ((lane >> 3) & 1) * 8;

    const unsigned As_u = (unsigned)__cvta_generic_to_shared(As);
    const unsigned Ws_u = (unsigned)__cvta_generic_to_shared(Ws);

    unsigned a_ad[4], b_ad[4];
#pragma unroll
    for (int mt = 0; mt < 4; mt++)
        a_ad[mt] = As_u + ((wm + mt * 16 + arow) * HSTR + acol) * 2u;
#pragma unroll
    for (int p = 0; p < 4; p++)
        b_ad[p] = Ws_u + ((wn + p * 16 + brow) * HSTR + bsel) * 2u;

    const __half* Abase = A + (size_t)bm * K;
    const __half* Wbase = W + (size_t)bn * K;

    float acc[4][8][4];
#pragma unroll
    for (int mt = 0; mt < 4; mt++)
#pragma unroll
        for (int nt = 0; nt < 8; nt++)
#pragma unroll
            for (int r = 0; r < 4; r++) acc[mt][nt][r] = 0.f;

    const int NIT = K / HBK;   // 16

#define G_FILL(sidx, koff)                                                    \
    do {                                                                      \
        __half* Ad = As + (sidx) * 128 * HSTR;                                \
        __half* Wd = Ws + (sidx) * 128 * HSTR;                                \
        _Pragma("unroll")                                                     \
        for (int i = 0; i < 8; i++) {                                         \
            const int idx = tid + i * 128;                                    \
            const int row = idx >> 3, c16 = idx & 7;                          \
            cp_async16(Ad + row * HSTR + c16 * 8,                             \
                       Abase + (size_t)row * K + (koff) + c16 * 8);           \
            cp_async16(Wd + row * HSTR + c16 * 8,                             \
                       Wbase + (size_t)row * K + (koff) + c16 * 8);           \
        }                                                                     \
        CP_COMMIT();                                                          \
    } while (0)

    G_FILL(0, 0);

    for (int it = 0; it < NIT; it++) {
        const int s = it & 1;
        CP_WAIT0();           // my stage-s copies (issued last iter) complete
        __syncthreads();      // all threads' stage-s data visible; stage 1-s free
        if (it + 1 < NIT)
            G_FILL(1 - s, (it + 1) * HBK);   // overlaps the compute below

        const unsigned so = (unsigned)(s * GSTG);
#pragma unroll
        for (int ks = 0; ks < 4; ks++) {
            const unsigned kb = so + ks * 32u;
            unsigned af[4][4];
#pragma unroll
            for (int mt = 0; mt < 4; mt++)
                LDSM4(af[mt][0], af[mt][1], af[mt][2], af[mt][3], a_ad[mt] + kb);
            unsigned bf[8][2];
#pragma unroll
            for (int p = 0; p < 4; p++)
                LDSM4(bf[2 * p][0], bf[2 * p][1], bf[2 * p + 1][0], bf[2 * p + 1][1],
                      b_ad[p] + kb);
#pragma unroll
            for (int mt = 0; mt < 4; mt++)
#pragma unroll
                for (int nt = 0; nt < 8; nt++)
                    mma_f16(acc[mt][nt][0], acc[mt][nt][1],
                            acc[mt][nt][2], acc[mt][nt][3],
                            af[mt][0], af[mt][1], af[mt][2], af[mt][3],
                            bf[nt][0], bf[nt][1]);
        }
    }
#undef G_FILL

#pragma unroll
    for (int nt = 0; nt < 8; nt++) {
        const int col = bn + wn + nt * 8 + 2 * qc;
        const float2 bv = *(const float2*)(bias + col);
#pragma unroll
        for (int mt = 0; mt < 4; mt++) {
            const int r0 = bm + wm + mt * 16 + qr;
            if (OUT_HALF) {
                __half* C = (__half*)Cv;
                *(__half2*)(C + (size_t)r0 * N + col) =
                    __floats2half2_rn(acc[mt][nt][0] + bv.x, acc[mt][nt][1] + bv.y);
                *(__half2*)(C + (size_t)(r0 + 8) * N + col) =
                    __floats2half2_rn(acc[mt][nt][2] + bv.x, acc[mt][nt][3] + bv.y);
            } else {
                float* C = (float*)Cv;
                *(float2*)(C + (size_t)r0 * N + col) =
                    make_float2(acc[mt][nt][0] + bv.x, acc[mt][nt][1] + bv.y);
                *(float2*)(C + (size_t)(r0 + 8) * N + col) =
                    make_float2(acc[mt][nt][2] + bv.x, acc[mt][nt][3] + bv.y);
            }
        }
    }
}

// ---------------------------------------------------------------------------
// FP16 flash attention v7: R12 structure (128 thr, 4 warps, warp tile 32x64,
// P-in-registers, Q hoisted) with ONE barrier per K/V tile and exp2-domain
// softmax (Q prescaled by 0.125*log2e; exp -> bare MUFU.EX2).
// ---------------------------------------------------------------------------
#define AQ   128
#define ASTR 72
#define KVSTG (64 * ASTR * 2)                  // 9216 bytes per K/V stage
#define ATT_SMEM ((AQ + 4 * 64) * ASTR * 2)    // 55296

__global__ __launch_bounds__(128) void attn_h(
    const __half* __restrict__ qkv, __half* __restrict__ out)
{
    extern __shared__ __half smh[];
    __half* Qs = smh;                          // 128 x 72
    __half* Ks = Qs + AQ * ASTR;               // 2 x 64 x 72
    __half* Vs = Ks + 2 * 64 * ASTR;           // 2 x 64 x 72

    const int bh = blockIdx.y;
    const int b  = bh >> 4;
    const int h  = bh & 15;
    const int q0 = blockIdx.x * AQ;

    const int tid  = threadIdx.x;
    const int lane = tid & 31;
    const int wid  = tid >> 5;
    const int wrow = wid * 32;
    const int qr = lane >> 2;
    const int qc = lane & 3;

    const int arow = lane & 15;
    const int acol = (lane >> 4) * 8;
    const int brow = (lane & 7) + 8 * (lane >> 4);
    const int bsel = ((lane >> 3) & 1) * 8;
    const int vrow = (lane & 7) + 8 * ((lane >> 3) & 1);
    const int vsel = (lane >> 4) * 8;

    const unsigned Qs_u = (unsigned)__cvta_generic_to_shared(Qs);
    const unsigned Ks_u = (unsigned)__cvta_generic_to_shared(Ks);
    const unsigned Vs_u = (unsigned)__cvta_generic_to_shared(Vs);

    unsigned q_ad[2], k_ad[4], v_ad[4];
#pragma unroll
    for (int mt = 0; mt < 2; mt++)
        q_ad[mt] = Qs_u + ((wrow + mt * 16 + arow) * ASTR + acol) * 2u;
#pragma unroll
    for (int p = 0; p < 4; p++) {
        k_ad[p] = Ks_u + ((p * 16 + brow) * ASTR + bsel) * 2u;
        v_ad[p] = Vs_u + (vrow * ASTR + p * 16 + vsel) * 2u;
    }

    const __half* base = qkv + (size_t)b * T_SZ * D3;
    const int hoff = h * DHEAD;

#define A_FILL(sidx, k0)                                                      \
    do {                                                                      \
        __half* Kd = Ks + (sidx) * 64 * ASTR;                                 \
        __half* Vd = Vs + (sidx) * 64 * ASTR;                                 \
        _Pragma("unroll")                                                     \
        for (int i = 0; i < 4; i++) {                                         \
            const int idx = tid + i * 128;                                    \
            const int row = idx >> 3, c8 = idx & 7;                           \
            const __half* rp = base + (size_t)((k0) + row) * D3 + hoff + c8 * 8; \
            cp_async16(Kd + row * ASTR + c8 * 8, rp + D_MODEL);               \
            cp_async16(Vd + row * ASTR + c8 * 8, rp + 2 * D_MODEL);           \
        }                                                                     \
        CP_COMMIT();                                                          \
    } while (0)

    // Load Q (128x64 halves), prescaled by 0.125*log2(e)  (exp2 domain)
    const __half2 qscale = __float2half2_rn(0.125f * 1.44269504088896f);
#pragma unroll
    for (int i = 0; i < 8; i++) {
        const int fidx = tid + i * 128;
        const int row = fidx >> 3;
        const int c8  = fidx & 7;
        const __half2* src = (const __half2*)(base + (size_t)(q0 + row) * D3 + hoff + c8 * 8);
        __half2* dst = (__half2*)(Qs + row * ASTR + c8 * 8);
        dst[0] = __hmul2(src[0], qscale);
        dst[1] = __hmul2(src[1], qscale);
        dst[2] = __hmul2(src[2], qscale);
        dst[3] = __hmul2(src[3], qscale);
    }

    A_FILL(0, 0);                              // prefetch K/V tile 0
    __syncthreads();                           // Q stores visible

    // Hoist loop-invariant Q A-fragments (4 ksteps x 2 mt)
    unsigned qf[4][2][4];
#pragma unroll
    for (int ks = 0; ks < 4; ks++)
#pragma unroll
        for (int mt = 0; mt < 2; mt++)
            LDSM4(qf[ks][mt][0], qf[ks][mt][1], qf[ks][mt][2], qf[ks][mt][3],
                  q_ad[mt] + ks * 32u);

    float mi[2][2], li[2][2];
#pragma unroll
    for (int mt = 0; mt < 2; mt++) {
        mi[mt][0] = -INFINITY; mi[mt][1] = -INFINITY;
        li[mt][0] = 0.f;       li[mt][1] = 0.f;
    }
    float oacc[2][8][4];
#pragma unroll
    for (int mt = 0; mt < 2; mt++)
#pragma unroll
        for (int nt = 0; nt < 8; nt++)
#pragma unroll
            for (int r = 0; r < 4; r++) oacc[mt][nt][r] = 0.f;

    const int NKT = T_SZ / 64;                 // 32 key tiles

    for (int kt = 0; kt < NKT; kt++) {
        const int s = kt & 1;
        CP_WAIT0();           // my stage-s copies complete
        __syncthreads();      // all visible; stage 1-s consumers done
        if (kt + 1 < NKT)
            A_FILL(1 - s, (kt + 1) * 64);      // overlaps compute below

        const unsigned soff = (unsigned)(s * KVSTG);

        // ---- S(log2 domain) = (Q*0.125*log2e) K^T ----
        float sacc[2][8][4];
#pragma unroll
        for (int mt = 0; mt < 2; mt++)
#pragma unroll
            for (int nt = 0; nt < 8; nt++)
#pragma unroll
                for (int r = 0; r < 4; r++) sacc[mt][nt][r] = 0.f;

#pragma unroll
        for (int ks = 0; ks < 4; ks++) {
            unsigned bf[8][2];
#pragma unroll
            for (int p = 0; p < 4; p++)
                LDSM4(bf[2 * p][0], bf[2 * p][1], bf[2 * p + 1][0], bf[2 * p + 1][1],
                      k_ad[p] + ks * 32u + soff);
#pragma unroll
            for (int nt = 0; nt < 8; nt++)
#pragma unroll
                for (int mt = 0; mt < 2; mt++)
                    mma_f16(sacc[mt][nt][0], sacc[mt][nt][1],
                            sacc[mt][nt][2], sacc[mt][nt][3],
                            qf[ks][mt][0], qf[ks][mt][1], qf[ks][mt][2], qf[ks][mt][3],
                            bf[nt][0], bf[nt][1]);
        }

        // ---- online softmax (exp2 domain); P stays in registers ----
        unsigned pf01[2][8], pf23[2][8];
#pragma unroll
        for (int mt = 0; mt < 2; mt++) {
            float mA = -INFINITY, mB = -INFINITY;
#pragma unroll
            for (int nt = 0; nt < 8; nt++) {
                mA = fmaxf(mA, fmaxf(sacc[mt][nt][0], sacc[mt][nt][1]));
                mB = fmaxf(mB, fmaxf(sacc[mt][nt][2], sacc[mt][nt][3]));
            }
            mA = fmaxf(mA, __shfl_xor_sync(0xffffffffu, mA, 1));
            mA = fmaxf(mA, __shfl_xor_sync(0xffffffffu, mA, 2));
            mB = fmaxf(mB, __shfl_xor_sync(0xffffffffu, mB, 1));
            mB = fmaxf(mB, __shfl_xor_sync(0xffffffffu, mB, 2));
            const float mnA = fmaxf(mi[mt][0], mA);
            const float mnB = fmaxf(mi[mt][1], mB);
            const float corrA = exp2f(mi[mt][0] - mnA);
            const float corrB = exp2f(mi[mt][1] - mnB);

            float psA = 0.f, psB = 0.f;
#pragma unroll
            for (int nt = 0; nt < 8; nt++) {
                __half2 h01 = __floats2half2_rn(exp2f(sacc[mt][nt][0] - mnA),
                                                exp2f(sacc[mt][nt][1] - mnA));
                __half2 h23 = __floats2half2_rn(exp2f(sacc[mt][nt][2] - mnB),
                                                exp2f(sacc[mt][nt][3] - mnB));
                pf01[mt][nt] = *(unsigned*)&h01;
                pf23[mt][nt] = *(unsigned*)&h23;
                float2 f01 = __half22float2(h01);
                float2 f23 = __half22float2(h23);
                psA += f01.x + f01.y;
                psB += f23.x + f23.y;
            }
            psA += __shfl_xor_sync(0xffffffffu, psA, 1);
            psA += __shfl_xor_sync(0xffffffffu, psA, 2);
            psB += __shfl_xor_sync(0xffffffffu, psB, 1);
            psB += __shfl_xor_sync(0xffffffffu, psB, 2);
            li[mt][0] = li[mt][0] * corrA + psA;
            li[mt][1] = li[mt][1] * corrB + psB;
            mi[mt][0] = mnA; mi[mt][1] = mnB;

#pragma unroll
            for (int nt = 0; nt < 8; nt++) {
                oacc[mt][nt][0] *= corrA; oacc[mt][nt][1] *= corrA;
                oacc[mt][nt][2] *= corrB; oacc[mt][nt][3] *= corrB;
            }
        }

        // ---- O += P V (P A-frags straight from registers) ----
#pragma unroll
        for (int ks = 0; ks < 4; ks++) {
            const unsigned kbV = ks * 16u * ASTR * 2u + soff;
            unsigned vf[8][2];
#pragma unroll
            for (int p = 0; p < 4; p++)
                LDSM4T(vf[2 * p][0], vf[2 * p][1], vf[2 * p + 1][0], vf[2 * p + 1][1],
                       v_ad[p] + kbV);
#pragma unroll
            for (int nt = 0; nt < 8; nt++)
#pragma unroll
                for (int mt = 0; mt < 2; mt++)
                    mma_f16(oacc[mt][nt][0], oacc[mt][nt][1],
                            oacc[mt][nt][2], oacc[mt][nt][3],
                            pf01[mt][2 * ks], pf23[mt][2 * ks],
                            pf01[mt][2 * ks + 1], pf23[mt][2 * ks + 1],
                            vf[nt][0], vf[nt][1]);
        }
    }
#undef A_FILL

    // epilogue -> fp16
#pragma unroll
    for (int mt = 0; mt < 2; mt++) {
        const float invA = 1.f / li[mt][0];
        const float invB = 1.f / li[mt][1];
        const int rowA = q0 + wrow + mt * 16 + qr;
        __half* opA = out + (size_t)(b * T_SZ + rowA) * D_MODEL + hoff;
        __half* opB = opA + (size_t)8 * D_MODEL;
#pragma unroll
        for (int nt = 0; nt < 8; nt++) {
            const int col = nt * 8 + 2 * qc;
            *(__half2*)(opA + col) =
                __floats2half2_rn(oacc[mt][nt][0] * invA, oacc[mt][nt][1] * invA);
            *(__half2*)(opB + col) =
                __floats2half2_rn(oacc[mt][nt][2] * invB, oacc[mt][nt][3] * invB);
        }
    }
}

// ---------------------------------------------------------------------------
// Launch
// ---------------------------------------------------------------------------
extern "C" void kernel_launch(void* const* d_in, const int* in_sizes, int n_in,
                              void* d_out, int out_size)
{
    const float* x     = (const float*)d_in[0];
    const float* qkv_w = (const float*)d_in[1];
    const float* qkv_b = (const float*)d_in[2];
    const float* out_w = (const float*)d_in[3];
    const float* out_b = (const float*)d_in[4];
    float* out = (float*)d_out;

    __half *qkvh, *atth, *xh, *wqh, *woh;
    cudaGetSymbolAddress((void**)&qkvh, g_qkvh);
    cudaGetSymbolAddress((void**)&atth, g_atth);
    cudaGetSymbolAddress((void**)&xh, g_xh);
    cudaGetSymbolAddress((void**)&wqh, g_wqh);
    cudaGetSymbolAddress((void**)&woh, g_woh);

    cudaFuncSetAttribute(gemm_h<true>, cudaFuncAttributeMaxDynamicSharedMemorySize,
                         GEMM_SMEM);
    cudaFuncSetAttribute(gemm_h<false>, cudaFuncAttributeMaxDynamicSharedMemorySize,
                         GEMM_SMEM);
    cudaFuncSetAttribute(attn_h, cudaFuncAttributeMaxDynamicSharedMemorySize,
                         ATT_SMEM);

    // 0) fp32 -> fp16 pre-pass
    {
        const int n1 = MROWS * D_MODEL / 4;
        const int n2 = D3 * D_MODEL / 4;
        const int n3 = D_MODEL * D_MODEL / 4;
        cvt_f32_f16<<<(n1 + 255) / 256, 256>>>(x, xh, n1);
        cvt_f32_f16<<<(n2 + 255) / 256, 256>>>(qkv_w, wqh, n2);
        cvt_f32_f16<<<(n3 + 255) / 256, 256>>>(out_w, woh, n3);
    }

    // 1) QKV projection -> fp16 qkv
    gemm_h<true><<<dim3(D3 / 128, MROWS / 128), 128, GEMM_SMEM>>>(
        xh, wqh, qkv_b, qkvh, MROWS, D3, D_MODEL);

    // 2) Attention -> fp16
    attn_h<<<dim3(T_SZ / AQ, B_SZ * NHEAD), 128, ATT_SMEM>>>(qkvh, atth);

    // 3) Output projection -> fp32 out
    gemm_h<false><<<dim3(D_MODEL / 128, MROWS / 128), 128, GEMM_SMEM>>>(
        atth, woh, out_b, out, MROWS, D_MODEL, D_MODEL);
}

// round 16
// speedup vs baseline: 1.1254x; 1.0557x over previous
#include <cuda_runtime.h>
#include <cuda_fp16.h>
#include <math.h>
#include <stdint.h>

// Problem constants
#define B_SZ    4
#define T_SZ    2048
#define D_MODEL 1024
#define NHEAD   16
#define DHEAD   64
#define D3      (3 * D_MODEL)
#define MROWS   (B_SZ * T_SZ)          // 8192

// Scratch (static device globals — allocation-free per harness rules)
__device__ __half g_qkvh[(size_t)MROWS * D3];       // fp16 qkv
__device__ __half g_atth[(size_t)MROWS * D_MODEL];  // fp16 attention out
__device__ __half g_xh[(size_t)MROWS * D_MODEL];    // fp16 x
__device__ __half g_wqh[(size_t)D3 * D_MODEL];      // fp16 qkv_w
__device__ __half g_woh[(size_t)D_MODEL * D_MODEL]; // fp16 out_w

// ---------------------------------------------------------------------------
// Helpers
// ---------------------------------------------------------------------------
__device__ __forceinline__ void mma_f16(
    float& d0, float& d1, float& d2, float& d3,
    unsigned a0, unsigned a1, unsigned a2, unsigned a3,
    unsigned b0, unsigned b1)
{
    asm("mma.sync.aligned.m16n8k16.row.col.f32.f16.f16.f32 "
        "{%0,%1,%2,%3}, {%4,%5,%6,%7}, {%8,%9}, {%0,%1,%2,%3};"
        : "+f"(d0), "+f"(d1), "+f"(d2), "+f"(d3)
        : "r"(a0), "r"(a1), "r"(a2), "r"(a3), "r"(b0), "r"(b1));
}

#define LDSM4(r0, r1, r2, r3, addr) \
    asm volatile("ldmatrix.sync.aligned.m8n8.x4.shared.b16 {%0,%1,%2,%3}, [%4];" \
                 : "=r"(r0), "=r"(r1), "=r"(r2), "=r"(r3) : "r"(addr))
#define LDSM4T(r0, r1, r2, r3, addr) \
    asm volatile("ldmatrix.sync.aligned.m8n8.x4.trans.shared.b16 {%0,%1,%2,%3}, [%4];" \
                 : "=r"(r0), "=r"(r1), "=r"(r2), "=r"(r3) : "r"(addr))

__device__ __forceinline__ void cp_async16(void* smem_dst, const void* gsrc) {
    unsigned saddr = (unsigned)__cvta_generic_to_shared(smem_dst);
    asm volatile("cp.async.ca.shared.global [%0], [%1], 16;"
                 :: "r"(saddr), "l"(gsrc));
}
#define CP_COMMIT()  asm volatile("cp.async.commit_group;")
#define CP_WAIT0()   asm volatile("cp.async.wait_group 0;")
#define CP_WAITG1()  asm volatile("cp.async.wait_group 1;")

// packed fp16 exp2
__device__ __forceinline__ unsigned h2exp2(unsigned x) {
    unsigned r;
    asm("ex2.approx.f16x2 %0, %1;" : "=r"(r) : "r"(x));
    return r;
}

// ---------------------------------------------------------------------------
// Fused pre-pass: fp32 -> fp16 (rn) for x, qkv_w, out_w in ONE launch.
// Index space is float4 units over the concatenation.
// ---------------------------------------------------------------------------
#define N1_F4 (MROWS * D_MODEL / 4)
#define N2_F4 (D3 * D_MODEL / 4)
#define N3_F4 (D_MODEL * D_MODEL / 4)

__global__ __launch_bounds__(256) void cvt_all_f16(
    const float* __restrict__ x, const float* __restrict__ wq,
    const float* __restrict__ wo,
    __half* __restrict__ xh, __half* __restrict__ wqh, __half* __restrict__ woh)
{
    int i = blockIdx.x * blockDim.x + threadIdx.x;
    const float* in;
    __half* out;
    int j;
    if (i < N1_F4)                 { in = x;  out = xh;  j = i; }
    else if (i < N1_F4 + N2_F4)    { in = wq; out = wqh; j = i - N1_F4; }
    else if (i < N1_F4 + N2_F4 + N3_F4) { in = wo; out = woh; j = i - N1_F4 - N2_F4; }
    else return;
    float4 v = ((const float4*)in)[j];
    ((__half2*)out)[2 * j]     = __floats2half2_rn(v.x, v.y);
    ((__half2*)out)[2 * j + 1] = __floats2half2_rn(v.z, v.w);
}

// ---------------------------------------------------------------------------
// FP16 GEMM v6 (unchanged from R14): 128 thr, 4 warps, warp tile 64x64,
// one barrier per K-chunk, 2-stage cp.async.
// ---------------------------------------------------------------------------
#define HBK 64
#define HSTR 72
#define GSTG (128 * HSTR * 2)                  // stage bytes: 18432
#define GEMM_SMEM (4 * GSTG)                   // 73728

template <bool OUT_HALF>
__global__ __launch_bounds__(128) void gemm_h(
    const __half* __restrict__ A, const __half* __restrict__ W,
    const float* __restrict__ bias, void* __restrict__ Cv,
    int M, int N, int K)
{
    extern __shared__ __half gsm[];
    __half* As = gsm;                          // [2][128][72]
    __half* Ws = gsm + 2 * 128 * HSTR;         // [2][128][72]

    const int tid  = threadIdx.x;
    const int lane = tid & 31;
    const int wid  = tid >> 5;
    const int wm = (wid >> 1) * 64;
    const int wn = (wid & 1) * 64;
    const int bm = blockIdx.y * 128;
    const int bn = blockIdx.x * 128;
    const int qr = lane >> 2;
    const int qc = lane & 3;

    const int arow = lane & 15;
    const int acol = (lane >> 4) * 8;
    const int brow = (lane & 7) + 8 * (lane >> 4);
    const int bsel = ((lane >> 3) & 1) * 8;

    const unsigned As_u = (unsigned)__cvta_generic_to_shared(As);
    const unsigned Ws_u = (unsigned)__cvta_generic_to_shared(Ws);

    unsigned a_ad[4], b_ad[4];
#pragma unroll
    for (int mt = 0; mt < 4; mt++)
        a_ad[mt] = As_u + ((wm + mt * 16 + arow) * HSTR + acol) * 2u;
#pragma unroll
    for (int p = 0; p < 4; p++)
        b_ad[p] = Ws_u + ((wn + p * 16 + brow) * HSTR + bsel) * 2u;

    const __half* Abase = A + (size_t)bm * K;
    const __half* Wbase = W + (size_t)bn * K;

    float acc[4][8][4];
#pragma unroll
    for (int mt = 0; mt < 4; mt++)
#pragma unroll
        for (int nt = 0; nt < 8; nt++)
#pragma unroll
            for (int r = 0; r < 4; r++) acc[mt][nt][r] = 0.f;

    const int NIT = K / HBK;   // 16

#define G_FILL(sidx, koff)                                                    \
    do {                                                                      \
        __half* Ad = As + (sidx) * 128 * HSTR;                                \
        __half* Wd = Ws + (sidx) * 128 * HSTR;                                \
        _Pragma("unroll")                                                     \
        for (int i = 0; i < 8; i++) {                                         \
            const int idx = tid + i * 128;                                    \
            const int row = idx >> 3, c16 = idx & 7;                          \
            cp_async16(Ad + row * HSTR + c16 * 8,                             \
                       Abase + (size_t)row * K + (koff) + c16 * 8);           \
            cp_async16(Wd + row * HSTR + c16 * 8,                             \
                       Wbase + (size_t)row * K + (koff) + c16 * 8);           \
        }                                                                     \
        CP_COMMIT();                                                          \
    } while (0)

    G_FILL(0, 0);

    for (int it = 0; it < NIT; it++) {
        const int s = it & 1;
        CP_WAIT0();
        __syncthreads();
        if (it + 1 < NIT)
            G_FILL(1 - s, (it + 1) * HBK);

        const unsigned so = (unsigned)(s * GSTG);
#pragma unroll
        for (int ks = 0; ks < 4; ks++) {
            const unsigned kb = so + ks * 32u;
            unsigned af[4][4];
#pragma unroll
            for (int mt = 0; mt < 4; mt++)
                LDSM4(af[mt][0], af[mt][1], af[mt][2], af[mt][3], a_ad[mt] + kb);
            unsigned bf[8][2];
#pragma unroll
            for (int p = 0; p < 4; p++)
                LDSM4(bf[2 * p][0], bf[2 * p][1], bf[2 * p + 1][0], bf[2 * p + 1][1],
                      b_ad[p] + kb);
#pragma unroll
            for (int mt = 0; mt < 4; mt++)
#pragma unroll
                for (int nt = 0; nt < 8; nt++)
                    mma_f16(acc[mt][nt][0], acc[mt][nt][1],
                            acc[mt][nt][2], acc[mt][nt][3],
                            af[mt][0], af[mt][1], af[mt][2], af[mt][3],
                            bf[nt][0], bf[nt][1]);
        }
    }
#undef G_FILL

#pragma unroll
    for (int nt = 0; nt < 8; nt++) {
        const int col = bn + wn + nt * 8 + 2 * qc;
        const float2 bv = *(const float2*)(bias + col);
#pragma unroll
        for (int mt = 0; mt < 4; mt++) {
            const int r0 = bm + wm + mt * 16 + qr;
            if (OUT_HALF) {
                __half* C = (__half*)Cv;
                *(__half2*)(C + (size_t)r0 * N + col) =
                    __floats2half2_rn(acc[mt][nt][0] + bv.x, acc[mt][nt][1] + bv.y);
                *(__half2*)(C + (size_t)(r0 + 8) * N + col) =
                    __floats2half2_rn(acc[mt][nt][2] + bv.x, acc[mt][nt][3] + bv.y);
            } else {
                float* C = (float*)Cv;
                *(float2*)(C + (size_t)r0 * N + col) =
                    make_float2(acc[mt][nt][0] + bv.x, acc[mt][nt][1] + bv.y);
                *(float2*)(C + (size_t)(r0 + 8) * N + col) =
                    make_float2(acc[mt][nt][2] + bv.x, acc[mt][nt][3] + bv.y);
            }
        }
    }
}

// ---------------------------------------------------------------------------
// FP16 flash attention v8: R14 structure + (a) 3-stage K/V ring with
// wait_group 1 (fills get 2 tiles of slack), (b) packed ex2.approx.f16x2
// softmax (MUFU ops per tile nearly halved).
// ---------------------------------------------------------------------------
#define AQ   128
#define ASTR 72
#define KVSTG (64 * ASTR * 2)                  // 9216 bytes per K/V stage
#define ATT_SMEM ((AQ + 6 * 64) * ASTR * 2)    // 73728

__global__ __launch_bounds__(128) void attn_h(
    const __half* __restrict__ qkv, __half* __restrict__ out)
{
    extern __shared__ __half smh[];
    __half* Qs = smh;                          // 128 x 72
    __half* Ks = Qs + AQ * ASTR;               // 3 x 64 x 72
    __half* Vs = Ks + 3 * 64 * ASTR;           // 3 x 64 x 72

    const int bh = blockIdx.y;
    const int b  = bh >> 4;
    const int h  = bh & 15;
    const int q0 = blockIdx.x * AQ;

    const int tid  = threadIdx.x;
    const int lane = tid & 31;
    const int wid  = tid >> 5;
    const int wrow = wid * 32;
    const int qr = lane >> 2;
    const int qc = lane & 3;

    const int arow = lane & 15;
    const int acol = (lane >> 4) * 8;
    const int brow = (lane & 7) + 8 * (lane >> 4);
    const int bsel = ((lane >> 3) & 1) * 8;
    const int vrow = (lane & 7) + 8 * ((lane >> 3) & 1);
    const int vsel = (lane >> 4) * 8;

    const unsigned Qs_u = (unsigned)__cvta_generic_to_shared(Qs);
    const unsigned Ks_u = (unsigned)__cvta_generic_to_shared(Ks);
    const unsigned Vs_u = (unsigned)__cvta_generic_to_shared(Vs);

    unsigned q_ad[2], k_ad[4], v_ad[4];
#pragma unroll
    for (int mt = 0; mt < 2; mt++)
        q_ad[mt] = Qs_u + ((wrow + mt * 16 + arow) * ASTR + acol) * 2u;
#pragma unroll
    for (int p = 0; p < 4; p++) {
        k_ad[p] = Ks_u + ((p * 16 + brow) * ASTR + bsel) * 2u;
        v_ad[p] = Vs_u + (vrow * ASTR + p * 16 + vsel) * 2u;
    }

    const __half* base = qkv + (size_t)b * T_SZ * D3;
    const int hoff = h * DHEAD;

#define A_FILL(sidx, k0)                                                      \
    do {                                                                      \
        __half* Kd = Ks + (sidx) * 64 * ASTR;                                 \
        __half* Vd = Vs + (sidx) * 64 * ASTR;                                 \
        _Pragma("unroll")                                                     \
        for (int i = 0; i < 4; i++) {                                         \
            const int idx = tid + i * 128;                                    \
            const int row = idx >> 3, c8 = idx & 7;                           \
            const __half* rp = base + (size_t)((k0) + row) * D3 + hoff + c8 * 8; \
            cp_async16(Kd + row * ASTR + c8 * 8, rp + D_MODEL);               \
            cp_async16(Vd + row * ASTR + c8 * 8, rp + 2 * D_MODEL);           \
        }                                                                     \
        CP_COMMIT();                                                          \
    } while (0)

    // Load Q (128x64 halves), prescaled by 0.125*log2(e)  (exp2 domain)
    const __half2 qscale = __float2half2_rn(0.125f * 1.44269504088896f);
#pragma unroll
    for (int i = 0; i < 8; i++) {
        const int fidx = tid + i * 128;
        const int row = fidx >> 3;
        const int c8  = fidx & 7;
        const __half2* src = (const __half2*)(base + (size_t)(q0 + row) * D3 + hoff + c8 * 8);
        __half2* dst = (__half2*)(Qs + row * ASTR + c8 * 8);
        dst[0] = __hmul2(src[0], qscale);
        dst[1] = __hmul2(src[1], qscale);
        dst[2] = __hmul2(src[2], qscale);
        dst[3] = __hmul2(src[3], qscale);
    }

    A_FILL(0, 0);                              // prefetch tiles 0 and 1
    A_FILL(1, 64);
    __syncthreads();                           // Q stores visible

    // Hoist loop-invariant Q A-fragments (4 ksteps x 2 mt)
    unsigned qf[4][2][4];
#pragma unroll
    for (int ks = 0; ks < 4; ks++)
#pragma unroll
        for (int mt = 0; mt < 2; mt++)
            LDSM4(qf[ks][mt][0], qf[ks][mt][1], qf[ks][mt][2], qf[ks][mt][3],
                  q_ad[mt] + ks * 32u);

    float mi[2][2], li[2][2];
#pragma unroll
    for (int mt = 0; mt < 2; mt++) {
        mi[mt][0] = -INFINITY; mi[mt][1] = -INFINITY;
        li[mt][0] = 0.f;       li[mt][1] = 0.f;
    }
    float oacc[2][8][4];
#pragma unroll
    for (int mt = 0; mt < 2; mt++)
#pragma unroll
        for (int nt = 0; nt < 8; nt++)
#pragma unroll
            for (int r = 0; r < 4; r++) oacc[mt][nt][r] = 0.f;

    const int NKT = T_SZ / 64;                 // 32 key tiles
    int stage = 0;

    for (int kt = 0; kt < NKT; kt++) {
        CP_WAITG1();          // fill(kt) done (fill(kt+1) may still be in flight)
        __syncthreads();      // all warps left tile kt-1; stage (kt+2)%3 free
        if (kt + 2 < NKT) {
            const int ns = (stage + 2 >= 3) ? stage - 1 : stage + 2;
            A_FILL(ns, (kt + 2) * 64);
        } else {
            CP_COMMIT();      // keep group alignment for wait_group 1
        }

        const unsigned soff = (unsigned)(stage * KVSTG);

        // ---- S(log2 domain) = (Q*0.125*log2e) K^T ----
        float sacc[2][8][4];
#pragma unroll
        for (int mt = 0; mt < 2; mt++)
#pragma unroll
            for (int nt = 0; nt < 8; nt++)
#pragma unroll
                for (int r = 0; r < 4; r++) sacc[mt][nt][r] = 0.f;

#pragma unroll
        for (int ks = 0; ks < 4; ks++) {
            unsigned bf[8][2];
#pragma unroll
            for (int p = 0; p < 4; p++)
                LDSM4(bf[2 * p][0], bf[2 * p][1], bf[2 * p + 1][0], bf[2 * p + 1][1],
                      k_ad[p] + ks * 32u + soff);
#pragma unroll
            for (int nt = 0; nt < 8; nt++)
#pragma unroll
                for (int mt = 0; mt < 2; mt++)
                    mma_f16(sacc[mt][nt][0], sacc[mt][nt][1],
                            sacc[mt][nt][2], sacc[mt][nt][3],
                            qf[ks][mt][0], qf[ks][mt][1], qf[ks][mt][2], qf[ks][mt][3],
                            bf[nt][0], bf[nt][1]);
        }

        // ---- online softmax (packed f16x2 ex2); P stays in registers ----
        unsigned pf01[2][8], pf23[2][8];
#pragma unroll
        for (int mt = 0; mt < 2; mt++) {
            float mA = -INFINITY, mB = -INFINITY;
#pragma unroll
            for (int nt = 0; nt < 8; nt++) {
                mA = fmaxf(mA, fmaxf(sacc[mt][nt][0], sacc[mt][nt][1]));
                mB = fmaxf(mB, fmaxf(sacc[mt][nt][2], sacc[mt][nt][3]));
            }
            mA = fmaxf(mA, __shfl_xor_sync(0xffffffffu, mA, 1));
            mA = fmaxf(mA, __shfl_xor_sync(0xffffffffu, mA, 2));
            mB = fmaxf(mB, __shfl_xor_sync(0xffffffffu, mB, 1));
            mB = fmaxf(mB, __shfl_xor_sync(0xffffffffu, mB, 2));
            const float mnA = fmaxf(mi[mt][0], mA);
            const float mnB = fmaxf(mi[mt][1], mB);
            const float corrA = exp2f(mi[mt][0] - mnA);
            const float corrB = exp2f(mi[mt][1] - mnB);

            float psA = 0.f, psB = 0.f;
#pragma unroll
            for (int nt = 0; nt < 8; nt++) {
                __half2 d01 = __floats2half2_rn(sacc[mt][nt][0] - mnA,
                                                sacc[mt][nt][1] - mnA);
                __half2 d23 = __floats2half2_rn(sacc[mt][nt][2] - mnB,
                                                sacc[mt][nt][3] - mnB);
                const unsigned p01 = h2exp2(*(unsigned*)&d01);
                const unsigned p23 = h2exp2(*(unsigned*)&d23);
                pf01[mt][nt] = p01;
                pf23[mt][nt] = p23;
                float2 f01 = __half22float2(*(__half2*)&p01);
                float2 f23 = __half22float2(*(__half2*)&p23);
                psA += f01.x + f01.y;
                psB += f23.x + f23.y;
            }
            psA += __shfl_xor_sync(0xffffffffu, psA, 1);
            psA += __shfl_xor_sync(0xffffffffu, psA, 2);
            psB += __shfl_xor_sync(0xffffffffu, psB, 1);
            psB += __shfl_xor_sync(0xffffffffu, psB, 2);
            li[mt][0] = li[mt][0] * corrA + psA;
            li[mt][1] = li[mt][1] * corrB + psB;
            mi[mt][0] = mnA; mi[mt][1] = mnB;

#pragma unroll
            for (int nt = 0; nt < 8; nt++) {
                oacc[mt][nt][0] *= corrA; oacc[mt][nt][1] *= corrA;
                oacc[mt][nt][2] *= corrB; oacc[mt][nt][3] *= corrB;
            }
        }

        // ---- O += P V (P A-frags straight from registers) ----
#pragma unroll
        for (int ks = 0; ks < 4; ks++) {
            const unsigned kbV = ks * 16u * ASTR * 2u + soff;
            unsigned vf[8][2];
#pragma unroll
            for (int p = 0; p < 4; p++)
                LDSM4T(vf[2 * p][0], vf[2 * p][1], vf[2 * p + 1][0], vf[2 * p + 1][1],
                       v_ad[p] + kbV);
#pragma unroll
            for (int nt = 0; nt < 8; nt++)
#pragma unroll
                for (int mt = 0; mt < 2; mt++)
                    mma_f16(oacc[mt][nt][0], oacc[mt][nt][1],
                            oacc[mt][nt][2], oacc[mt][nt][3],
                            pf01[mt][2 * ks], pf23[mt][2 * ks],
                            pf01[mt][2 * ks + 1], pf23[mt][2 * ks + 1],
                            vf[nt][0], vf[nt][1]);
        }

        stage = (stage + 1 >= 3) ? 0 : stage + 1;
    }
#undef A_FILL

    // epilogue -> fp16
#pragma unroll
    for (int mt = 0; mt < 2; mt++) {
        const float invA = 1.f / li[mt][0];
        const float invB = 1.f / li[mt][1];
        const int rowA = q0 + wrow + mt * 16 + qr;
        __half* opA = out + (size_t)(b * T_SZ + rowA) * D_MODEL + hoff;
        __half* opB = opA + (size_t)8 * D_MODEL;
#pragma unroll
        for (int nt = 0; nt < 8; nt++) {
            const int col = nt * 8 + 2 * qc;
            *(__half2*)(opA + col) =
                __floats2half2_rn(oacc[mt][nt][0] * invA, oacc[mt][nt][1] * invA);
            *(__half2*)(opB + col) =
                __floats2half2_rn(oacc[mt][nt][2] * invB, oacc[mt][nt][3] * invB);
        }
    }
}

// ---------------------------------------------------------------------------
// Launch
// ---------------------------------------------------------------------------
extern "C" void kernel_launch(void* const* d_in, const int* in_sizes, int n_in,
                              void* d_out, int out_size)
{
    const float* x     = (const float*)d_in[0];
    const float* qkv_w = (const float*)d_in[1];
    const float* qkv_b = (const float*)d_in[2];
    const float* out_w = (const float*)d_in[3];
    const float* out_b = (const float*)d_in[4];
    float* out = (float*)d_out;

    __half *qkvh, *atth, *xh, *wqh, *woh;
    cudaGetSymbolAddress((void**)&qkvh, g_qkvh);
    cudaGetSymbolAddress((void**)&atth, g_atth);
    cudaGetSymbolAddress((void**)&xh, g_xh);
    cudaGetSymbolAddress((void**)&wqh, g_wqh);
    cudaGetSymbolAddress((void**)&woh, g_woh);

    cudaFuncSetAttribute(gemm_h<true>, cudaFuncAttributeMaxDynamicSharedMemorySize,
                         GEMM_SMEM);
    cudaFuncSetAttribute(gemm_h<false>, cudaFuncAttributeMaxDynamicSharedMemorySize,
                         GEMM_SMEM);
    cudaFuncSetAttribute(attn_h, cudaFuncAttributeMaxDynamicSharedMemorySize,
                         ATT_SMEM);

    // 0) fused fp32 -> fp16 pre-pass (x, qkv_w, out_w in one launch)
    {
        const int total = N1_F4 + N2_F4 + N3_F4;
        cvt_all_f16<<<(total + 255) / 256, 256>>>(x, qkv_w, out_w, xh, wqh, woh);
    }

    // 1) QKV projection -> fp16 qkv
    gemm_h<true><<<dim3(D3 / 128, MROWS / 128), 128, GEMM_SMEM>>>(
        xh, wqh, qkv_b, qkvh, MROWS, D3, D_MODEL);

    // 2) Attention -> fp16
    attn_h<<<dim3(T_SZ / AQ, B_SZ * NHEAD), 128, ATT_SMEM>>>(qkvh, atth);

    // 3) Output projection -> fp32 out
    gemm_h<false><<<dim3(D_MODEL / 128, MROWS / 128), 128, GEMM_SMEM>>>(
        atth, woh, out_b, out, MROWS, D_MODEL, D_MODEL);
}

// round 17
// speedup vs baseline: 1.1399x; 1.0129x over previous
#include <cuda_runtime.h>
#include <cuda_fp16.h>
#include <math.h>
#include <stdint.h>

// Problem constants
#define B_SZ    4
#define T_SZ    2048
#define D_MODEL 1024
#define NHEAD   16
#define DHEAD   64
#define D3      (3 * D_MODEL)
#define MROWS   (B_SZ * T_SZ)          // 8192

// Scratch (static device globals — allocation-free per harness rules)
__device__ __half g_qkvh[(size_t)MROWS * D3];       // fp16 qkv
__device__ __half g_atth[(size_t)MROWS * D_MODEL];  // fp16 attention out
__device__ __half g_xh[(size_t)MROWS * D_MODEL];    // fp16 x
__device__ __half g_wqh[(size_t)D3 * D_MODEL];      // fp16 qkv_w
__device__ __half g_woh[(size_t)D_MODEL * D_MODEL]; // fp16 out_w

// ---------------------------------------------------------------------------
// Helpers
// ---------------------------------------------------------------------------
__device__ __forceinline__ void mma_f16(
    float& d0, float& d1, float& d2, float& d3,
    unsigned a0, unsigned a1, unsigned a2, unsigned a3,
    unsigned b0, unsigned b1)
{
    asm("mma.sync.aligned.m16n8k16.row.col.f32.f16.f16.f32 "
        "{%0,%1,%2,%3}, {%4,%5,%6,%7}, {%8,%9}, {%0,%1,%2,%3};"
        : "+f"(d0), "+f"(d1), "+f"(d2), "+f"(d3)
        : "r"(a0), "r"(a1), "r"(a2), "r"(a3), "r"(b0), "r"(b1));
}

#define LDSM4(r0, r1, r2, r3, addr) \
    asm volatile("ldmatrix.sync.aligned.m8n8.x4.shared.b16 {%0,%1,%2,%3}, [%4];" \
                 : "=r"(r0), "=r"(r1), "=r"(r2), "=r"(r3) : "r"(addr))
#define LDSM4T(r0, r1, r2, r3, addr) \
    asm volatile("ldmatrix.sync.aligned.m8n8.x4.trans.shared.b16 {%0,%1,%2,%3}, [%4];" \
                 : "=r"(r0), "=r"(r1), "=r"(r2), "=r"(r3) : "r"(addr))

__device__ __forceinline__ void cp_async16(void* smem_dst, const void* gsrc) {
    unsigned saddr = (unsigned)__cvta_generic_to_shared(smem_dst);
    asm volatile("cp.async.ca.shared.global [%0], [%1], 16;"
                 :: "r"(saddr), "l"(gsrc));
}
#define CP_COMMIT()  asm volatile("cp.async.commit_group;")
#define CP_WAIT0()   asm volatile("cp.async.wait_group 0;")
#define CP_WAITG1()  asm volatile("cp.async.wait_group 1;")

// packed fp16 exp2
__device__ __forceinline__ unsigned h2exp2(unsigned x) {
    unsigned r;
    asm("ex2.approx.f16x2 %0, %1;" : "=r"(r) : "r"(x));
    return r;
}

// ---------------------------------------------------------------------------
// Fused pre-pass: fp32 -> fp16 (rn) for x, qkv_w, out_w in ONE launch.
// ---------------------------------------------------------------------------
#define N1_F4 (MROWS * D_MODEL / 4)
#define N2_F4 (D3 * D_MODEL / 4)
#define N3_F4 (D_MODEL * D_MODEL / 4)

__global__ __launch_bounds__(256) void cvt_all_f16(
    const float* __restrict__ x, const float* __restrict__ wq,
    const float* __restrict__ wo,
    __half* __restrict__ xh, __half* __restrict__ wqh, __half* __restrict__ woh)
{
    int i = blockIdx.x * blockDim.x + threadIdx.x;
    const float* in;
    __half* out;
    int j;
    if (i < N1_F4)                 { in = x;  out = xh;  j = i; }
    else if (i < N1_F4 + N2_F4)    { in = wq; out = wqh; j = i - N1_F4; }
    else if (i < N1_F4 + N2_F4 + N3_F4) { in = wo; out = woh; j = i - N1_F4 - N2_F4; }
    else return;
    float4 v = ((const float4*)in)[j];
    ((__half2*)out)[2 * j]     = __floats2half2_rn(v.x, v.y);
    ((__half2*)out)[2 * j + 1] = __floats2half2_rn(v.z, v.w);
}

// ---------------------------------------------------------------------------
// FP16 GEMM v7: v6 + register double-buffered B fragments (bf for kstep ks+1
// loads while kstep ks's mma stream issues). One barrier per K-chunk,
// 2-stage cp.async, stride-72 conflict-free ldmatrix.
// ---------------------------------------------------------------------------
#define HBK 64
#define HSTR 72
#define GSTG (128 * HSTR * 2)                  // stage bytes: 18432
#define GEMM_SMEM (4 * GSTG)                   // 73728

template <bool OUT_HALF>
__global__ __launch_bounds__(128) void gemm_h(
    const __half* __restrict__ A, const __half* __restrict__ W,
    const float* __restrict__ bias, void* __restrict__ Cv,
    int M, int N, int K)
{
    extern __shared__ __half gsm[];
    __half* As = gsm;                          // [2][128][72]
    __half* Ws = gsm + 2 * 128 * HSTR;         // [2][128][72]

    const int tid  = threadIdx.x;
    const int lane = tid & 31;
    const int wid  = tid >> 5;
    const int wm = (wid >> 1) * 64;
    const int wn = (wid & 1) * 64;
    const int bm = blockIdx.y * 128;
    const int bn = blockIdx.x * 128;
    const int qr = lane >> 2;
    const int qc = lane & 3;

    const int arow = lane & 15;
    const int acol = (lane >> 4) * 8;
    const int brow = (lane & 7) + 8 * (lane >> 4);
    const int bsel = ((lane >> 3) & 1) * 8;

    const unsigned As_u = (unsigned)__cvta_generic_to_shared(As);
    const unsigned Ws_u = (unsigned)__cvta_generic_to_shared(Ws);

    unsigned a_ad[4], b_ad[4];
#pragma unroll
    for (int mt = 0; mt < 4; mt++)
        a_ad[mt] = As_u + ((wm + mt * 16 + arow) * HSTR + acol) * 2u;
#pragma unroll
    for (int p = 0; p < 4; p++)
        b_ad[p] = Ws_u + ((wn + p * 16 + brow) * HSTR + bsel) * 2u;

    const __half* Abase = A + (size_t)bm * K;
    const __half* Wbase = W + (size_t)bn * K;

    float acc[4][8][4];
#pragma unroll
    for (int mt = 0; mt < 4; mt++)
#pragma unroll
        for (int nt = 0; nt < 8; nt++)
#pragma unroll
            for (int r = 0; r < 4; r++) acc[mt][nt][r] = 0.f;

    const int NIT = K / HBK;   // 16

#define G_FILL(sidx, koff)                                                    \
    do {                                                                      \
        __half* Ad = As + (sidx) * 128 * HSTR;                                \
        __half* Wd = Ws + (sidx) * 128 * HSTR;                                \
        _Pragma("unroll")                                                     \
        for (int i = 0; i < 8; i++) {                                         \
            const int idx = tid + i * 128;                                    \
            const int row = idx >> 3, c16 = idx & 7;                          \
            cp_async16(Ad + row * HSTR + c16 * 8,                             \
                       Abase + (size_t)row * K + (koff) + c16 * 8);           \
            cp_async16(Wd + row * HSTR + c16 * 8,                             \
                       Wbase + (size_t)row * K + (koff) + c16 * 8);           \
        }                                                                     \
        CP_COMMIT();                                                          \
    } while (0)

    G_FILL(0, 0);

    for (int it = 0; it < NIT; it++) {
        const int s = it & 1;
        CP_WAIT0();
        __syncthreads();
        if (it + 1 < NIT)
            G_FILL(1 - s, (it + 1) * HBK);

        const unsigned so = (unsigned)(s * GSTG);

        // double-buffered B fragments: preload ks=0
        unsigned bf[2][8][2];
#pragma unroll
        for (int p = 0; p < 4; p++)
            LDSM4(bf[0][2 * p][0], bf[0][2 * p][1],
                  bf[0][2 * p + 1][0], bf[0][2 * p + 1][1], b_ad[p] + so);

#pragma unroll
        for (int ks = 0; ks < 4; ks++) {
            const int cur = ks & 1;
            const unsigned kb = so + ks * 32u;
            unsigned af[4][4];
#pragma unroll
            for (int mt = 0; mt < 4; mt++)
                LDSM4(af[mt][0], af[mt][1], af[mt][2], af[mt][3], a_ad[mt] + kb);
            if (ks < 3) {
#pragma unroll
                for (int p = 0; p < 4; p++)
                    LDSM4(bf[1 - cur][2 * p][0], bf[1 - cur][2 * p][1],
                          bf[1 - cur][2 * p + 1][0], bf[1 - cur][2 * p + 1][1],
                          b_ad[p] + kb + 32u);
            }
#pragma unroll
            for (int mt = 0; mt < 4; mt++)
#pragma unroll
                for (int nt = 0; nt < 8; nt++)
                    mma_f16(acc[mt][nt][0], acc[mt][nt][1],
                            acc[mt][nt][2], acc[mt][nt][3],
                            af[mt][0], af[mt][1], af[mt][2], af[mt][3],
                            bf[cur][nt][0], bf[cur][nt][1]);
        }
    }
#undef G_FILL

#pragma unroll
    for (int nt = 0; nt < 8; nt++) {
        const int col = bn + wn + nt * 8 + 2 * qc;
        const float2 bv = *(const float2*)(bias + col);
#pragma unroll
        for (int mt = 0; mt < 4; mt++) {
            const int r0 = bm + wm + mt * 16 + qr;
            if (OUT_HALF) {
                __half* C = (__half*)Cv;
                *(__half2*)(C + (size_t)r0 * N + col) =
                    __floats2half2_rn(acc[mt][nt][0] + bv.x, acc[mt][nt][1] + bv.y);
                *(__half2*)(C + (size_t)(r0 + 8) * N + col) =
                    __floats2half2_rn(acc[mt][nt][2] + bv.x, acc[mt][nt][3] + bv.y);
            } else {
                float* C = (float*)Cv;
                *(float2*)(C + (size_t)r0 * N + col) =
                    make_float2(acc[mt][nt][0] + bv.x, acc[mt][nt][1] + bv.y);
                *(float2*)(C + (size_t)(r0 + 8) * N + col) =
                    make_float2(acc[mt][nt][2] + bv.x, acc[mt][nt][3] + bv.y);
            }
        }
    }
}

// ---------------------------------------------------------------------------
// FP16 flash attention v9: v8 + deferred l-reduction. corr factors are
// quad-uniform (row max is shuffled), so each thread carries a per-thread
// partial l; the quad sum-reduction happens ONCE in the epilogue. Removes
// all in-loop sum shuffles (16 SHFL + 2 serial shuffle rounds per tile).
// ---------------------------------------------------------------------------
#define AQ   128
#define ASTR 72
#define KVSTG (64 * ASTR * 2)                  // 9216 bytes per K/V stage
#define ATT_SMEM ((AQ + 6 * 64) * ASTR * 2)    // 73728

__global__ __launch_bounds__(128) void attn_h(
    const __half* __restrict__ qkv, __half* __restrict__ out)
{
    extern __shared__ __half smh[];
    __half* Qs = smh;                          // 128 x 72
    __half* Ks = Qs + AQ * ASTR;               // 3 x 64 x 72
    __half* Vs = Ks + 3 * 64 * ASTR;           // 3 x 64 x 72

    const int bh = blockIdx.y;
    const int b  = bh >> 4;
    const int h  = bh & 15;
    const int q0 = blockIdx.x * AQ;

    const int tid  = threadIdx.x;
    const int lane = tid & 31;
    const int wid  = tid >> 5;
    const int wrow = wid * 32;
    const int qr = lane >> 2;
    const int qc = lane & 3;

    const int arow = lane & 15;
    const int acol = (lane >> 4) * 8;
    const int brow = (lane & 7) + 8 * (lane >> 4);
    const int bsel = ((lane >> 3) & 1) * 8;
    const int vrow = (lane & 7) + 8 * ((lane >> 3) & 1);
    const int vsel = (lane >> 4) * 8;

    const unsigned Qs_u = (unsigned)__cvta_generic_to_shared(Qs);
    const unsigned Ks_u = (unsigned)__cvta_generic_to_shared(Ks);
    const unsigned Vs_u = (unsigned)__cvta_generic_to_shared(Vs);

    unsigned q_ad[2], k_ad[4], v_ad[4];
#pragma unroll
    for (int mt = 0; mt < 2; mt++)
        q_ad[mt] = Qs_u + ((wrow + mt * 16 + arow) * ASTR + acol) * 2u;
#pragma unroll
    for (int p = 0; p < 4; p++) {
        k_ad[p] = Ks_u + ((p * 16 + brow) * ASTR + bsel) * 2u;
        v_ad[p] = Vs_u + (vrow * ASTR + p * 16 + vsel) * 2u;
    }

    const __half* base = qkv + (size_t)b * T_SZ * D3;
    const int hoff = h * DHEAD;

#define A_FILL(sidx, k0)                                                      \
    do {                                                                      \
        __half* Kd = Ks + (sidx) * 64 * ASTR;                                 \
        __half* Vd = Vs + (sidx) * 64 * ASTR;                                 \
        _Pragma("unroll")                                                     \
        for (int i = 0; i < 4; i++) {                                         \
            const int idx = tid + i * 128;                                    \
            const int row = idx >> 3, c8 = idx & 7;                           \
            const __half* rp = base + (size_t)((k0) + row) * D3 + hoff + c8 * 8; \
            cp_async16(Kd + row * ASTR + c8 * 8, rp + D_MODEL);               \
            cp_async16(Vd + row * ASTR + c8 * 8, rp + 2 * D_MODEL);           \
        }                                                                     \
        CP_COMMIT();                                                          \
    } while (0)

    // Load Q (128x64 halves), prescaled by 0.125*log2(e)  (exp2 domain)
    const __half2 qscale = __float2half2_rn(0.125f * 1.44269504088896f);
#pragma unroll
    for (int i = 0; i < 8; i++) {
        const int fidx = tid + i * 128;
        const int row = fidx >> 3;
        const int c8  = fidx & 7;
        const __half2* src = (const __half2*)(base + (size_t)(q0 + row) * D3 + hoff + c8 * 8);
        __half2* dst = (__half2*)(Qs + row * ASTR + c8 * 8);
        dst[0] = __hmul2(src[0], qscale);
        dst[1] = __hmul2(src[1], qscale);
        dst[2] = __hmul2(src[2], qscale);
        dst[3] = __hmul2(src[3], qscale);
    }

    A_FILL(0, 0);                              // prefetch tiles 0 and 1
    A_FILL(1, 64);
    __syncthreads();                           // Q stores visible

    // Hoist loop-invariant Q A-fragments (4 ksteps x 2 mt)
    unsigned qf[4][2][4];
#pragma unroll
    for (int ks = 0; ks < 4; ks++)
#pragma unroll
        for (int mt = 0; mt < 2; mt++)
            LDSM4(qf[ks][mt][0], qf[ks][mt][1], qf[ks][mt][2], qf[ks][mt][3],
                  q_ad[mt] + ks * 32u);

    float mi[2][2], li[2][2];                  // li = PER-THREAD partial sums
#pragma unroll
    for (int mt = 0; mt < 2; mt++) {
        mi[mt][0] = -INFINITY; mi[mt][1] = -INFINITY;
        li[mt][0] = 0.f;       li[mt][1] = 0.f;
    }
    float oacc[2][8][4];
#pragma unroll
    for (int mt = 0; mt < 2; mt++)
#pragma unroll
        for (int nt = 0; nt < 8; nt++)
#pragma unroll
            for (int r = 0; r < 4; r++) oacc[mt][nt][r] = 0.f;

    const int NKT = T_SZ / 64;                 // 32 key tiles
    int stage = 0;

    for (int kt = 0; kt < NKT; kt++) {
        CP_WAITG1();          // fill(kt) done (fill(kt+1) may still be in flight)
        __syncthreads();      // all warps left tile kt-1; stage (kt+2)%3 free
        if (kt + 2 < NKT) {
            const int ns = (stage + 2 >= 3) ? stage - 1 : stage + 2;
            A_FILL(ns, (kt + 2) * 64);
        } else {
            CP_COMMIT();      // keep group alignment for wait_group 1
        }

        const unsigned soff = (unsigned)(stage * KVSTG);

        // ---- S(log2 domain) = (Q*0.125*log2e) K^T ----
        float sacc[2][8][4];
#pragma unroll
        for (int mt = 0; mt < 2; mt++)
#pragma unroll
            for (int nt = 0; nt < 8; nt++)
#pragma unroll
                for (int r = 0; r < 4; r++) sacc[mt][nt][r] = 0.f;

#pragma unroll
        for (int ks = 0; ks < 4; ks++) {
            unsigned bf[8][2];
#pragma unroll
            for (int p = 0; p < 4; p++)
                LDSM4(bf[2 * p][0], bf[2 * p][1], bf[2 * p + 1][0], bf[2 * p + 1][1],
                      k_ad[p] + ks * 32u + soff);
#pragma unroll
            for (int nt = 0; nt < 8; nt++)
#pragma unroll
                for (int mt = 0; mt < 2; mt++)
                    mma_f16(sacc[mt][nt][0], sacc[mt][nt][1],
                            sacc[mt][nt][2], sacc[mt][nt][3],
                            qf[ks][mt][0], qf[ks][mt][1], qf[ks][mt][2], qf[ks][mt][3],
                            bf[nt][0], bf[nt][1]);
        }

        // ---- online softmax (packed f16x2 ex2); l kept per-thread ----
        unsigned pf01[2][8], pf23[2][8];
#pragma unroll
        for (int mt = 0; mt < 2; mt++) {
            float mA = -INFINITY, mB = -INFINITY;
#pragma unroll
            for (int nt = 0; nt < 8; nt++) {
                mA = fmaxf(mA, fmaxf(sacc[mt][nt][0], sacc[mt][nt][1]));
                mB = fmaxf(mB, fmaxf(sacc[mt][nt][2], sacc[mt][nt][3]));
            }
            mA = fmaxf(mA, __shfl_xor_sync(0xffffffffu, mA, 1));
            mA = fmaxf(mA, __shfl_xor_sync(0xffffffffu, mA, 2));
            mB = fmaxf(mB, __shfl_xor_sync(0xffffffffu, mB, 1));
            mB = fmaxf(mB, __shfl_xor_sync(0xffffffffu, mB, 2));
            const float mnA = fmaxf(mi[mt][0], mA);
            const float mnB = fmaxf(mi[mt][1], mB);
            const float corrA = exp2f(mi[mt][0] - mnA);
            const float corrB = exp2f(mi[mt][1] - mnB);

            float psA = 0.f, psB = 0.f;
#pragma unroll
            for (int nt = 0; nt < 8; nt++) {
                __half2 d01 = __floats2half2_rn(sacc[mt][nt][0] - mnA,
                                                sacc[mt][nt][1] - mnA);
                __half2 d23 = __floats2half2_rn(sacc[mt][nt][2] - mnB,
                                                sacc[mt][nt][3] - mnB);
                const unsigned p01 = h2exp2(*(unsigned*)&d01);
                const unsigned p23 = h2exp2(*(unsigned*)&d23);
                pf01[mt][nt] = p01;
                pf23[mt][nt] = p23;
                float2 f01 = __half22float2(*(__half2*)&p01);
                float2 f23 = __half22float2(*(__half2*)&p23);
                psA += f01.x + f01.y;
                psB += f23.x + f23.y;
            }
            // per-thread partials only; quad reduction deferred to epilogue
            li[mt][0] = li[mt][0] * corrA + psA;
            li[mt][1] = li[mt][1] * corrB + psB;
            mi[mt][0] = mnA; mi[mt][1] = mnB;

#pragma unroll
            for (int nt = 0; nt < 8; nt++) {
                oacc[mt][nt][0] *= corrA; oacc[mt][nt][1] *= corrA;
                oacc[mt][nt][2] *= corrB; oacc[mt][nt][3] *= corrB;
            }
        }

        // ---- O += P V (P A-frags straight from registers) ----
#pragma unroll
        for (int ks = 0; ks < 4; ks++) {
            const unsigned kbV = ks * 16u * ASTR * 2u + soff;
            unsigned vf[8][2];
#pragma unroll
            for (int p = 0; p < 4; p++)
                LDSM4T(vf[2 * p][0], vf[2 * p][1], vf[2 * p + 1][0], vf[2 * p + 1][1],
                       v_ad[p] + kbV);
#pragma unroll
            for (int nt = 0; nt < 8; nt++)
#pragma unroll
                for (int mt = 0; mt < 2; mt++)
                    mma_f16(oacc[mt][nt][0], oacc[mt][nt][1],
                            oacc[mt][nt][2], oacc[mt][nt][3],
                            pf01[mt][2 * ks], pf23[mt][2 * ks],
                            pf01[mt][2 * ks + 1], pf23[mt][2 * ks + 1],
                            vf[nt][0], vf[nt][1]);
        }

        stage = (stage + 1 >= 3) ? 0 : stage + 1;
    }
#undef A_FILL

    // epilogue: quad-reduce the deferred l partials, then scale + store fp16
#pragma unroll
    for (int mt = 0; mt < 2; mt++) {
        float lA = li[mt][0], lB = li[mt][1];
        lA += __shfl_xor_sync(0xffffffffu, lA, 1);
        lA += __shfl_xor_sync(0xffffffffu, lA, 2);
        lB += __shfl_xor_sync(0xffffffffu, lB, 1);
        lB += __shfl_xor_sync(0xffffffffu, lB, 2);
        const float invA = 1.f / lA;
        const float invB = 1.f / lB;
        const int rowA = q0 + wrow + mt * 16 + qr;
        __half* opA = out + (size_t)(b * T_SZ + rowA) * D_MODEL + hoff;
        __half* opB = opA + (size_t)8 * D_MODEL;
#pragma unroll
        for (int nt = 0; nt < 8; nt++) {
            const int col = nt * 8 + 2 * qc;
            *(__half2*)(opA + col) =
                __floats2half2_rn(oacc[mt][nt][0] * invA, oacc[mt][nt][1] * invA);
            *(__half2*)(opB + col) =
                __floats2half2_rn(oacc[mt][nt][2] * invB, oacc[mt][nt][3] * invB);
        }
    }
}

// ---------------------------------------------------------------------------
// Launch
// ---------------------------------------------------------------------------
extern "C" void kernel_launch(void* const* d_in, const int* in_sizes, int n_in,
                              void* d_out, int out_size)
{
    const float* x     = (const float*)d_in[0];
    const float* qkv_w = (const float*)d_in[1];
    const float* qkv_b = (const float*)d_in[2];
    const float* out_w = (const float*)d_in[3];
    const float* out_b = (const float*)d_in[4];
    float* out = (float*)d_out;

    __half *qkvh, *atth, *xh, *wqh, *woh;
    cudaGetSymbolAddress((void**)&qkvh, g_qkvh);
    cudaGetSymbolAddress((void**)&atth, g_atth);
    cudaGetSymbolAddress((void**)&xh, g_xh);
    cudaGetSymbolAddress((void**)&wqh, g_wqh);
    cudaGetSymbolAddress((void**)&woh, g_woh);

    cudaFuncSetAttribute(gemm_h<true>, cudaFuncAttributeMaxDynamicSharedMemorySize,
                         GEMM_SMEM);
    cudaFuncSetAttribute(gemm_h<false>, cudaFuncAttributeMaxDynamicSharedMemorySize,
                         GEMM_SMEM);
    cudaFuncSetAttribute(attn_h, cudaFuncAttributeMaxDynamicSharedMemorySize,
                         ATT_SMEM);

    // 0) fused fp32 -> fp16 pre-pass (x, qkv_w, out_w in one launch)
    {
        const int total = N1_F4 + N2_F4 + N3_F4;
        cvt_all_f16<<<(total + 255) / 256, 256>>>(x, qkv_w, out_w, xh, wqh, woh);
    }

    // 1) QKV projection -> fp16 qkv
    gemm_h<true><<<dim3(D3 / 128, MROWS / 128), 128, GEMM_SMEM>>>(
        xh, wqh, qkv_b, qkvh, MROWS, D3, D_MODEL);

    // 2) Attention -> fp16
    attn_h<<<dim3(T_SZ / AQ, B_SZ * NHEAD), 128, ATT_SMEM>>>(qkvh, atth);

    // 3) Output projection -> fp32 out
    gemm_h<false><<<dim3(D_MODEL / 128, MROWS / 128), 128, GEMM_SMEM>>>(
        atth, woh, out_b, out, MROWS, D_MODEL, D_MODEL);
}